// round 5
// baseline (speedup 1.0000x reference)
#include <cuda_runtime.h>
#include <cstdint>

#define NROWS   256
#define TM1     131072                    // outputs per row
#define TROW    131073                    // edc row length
#define CHUNK   4096
#define CH_ROW  (TM1 / CHUNK)             // 32 chunks per row
#define NCHUNKS (NROWS * CH_ROW)          // 8192
#define NGROUPS ((size_t)NROWS * TM1 / 4) // 8,388,608 4-output groups

// Scratch (static device arrays — no runtime allocation).
// byte layout: bits[0:3] = 4 flip bits of the group,
//              bit 4     = exclusive flip-parity of the group within its chunk
__device__ unsigned char g_packed[NGROUPS];          // 8.4 MB
__device__ unsigned int  g_chunkpar[NCHUNKS];        // 32 KB (0/1 per chunk)

// ---------------------------------------------------------------------------
// Kernel 1: read flips once, emit packed bits + per-chunk parity.
// One CTA (1024 thr) per 4096-element chunk; grid = 8192.
// ---------------------------------------------------------------------------
__global__ void __launch_bounds__(1024)
pack_kernel(const int* __restrict__ flips)
{
    const int g    = blockIdx.x;                 // chunk id (row = g/32)
    const int tid  = threadIdx.x;
    const int lane = tid & 31;
    const int warp = tid >> 5;
    const uint32_t ltmask = (1u << lane) - 1u;

    const int4 f = __ldg(reinterpret_cast<const int4*>(flips) + (size_t)g * 1024 + tid);
    uint32_t p0 = (uint32_t)f.x & 1u;
    uint32_t p1 = (uint32_t)f.y & 1u;
    uint32_t p2 = (uint32_t)f.z & 1u;
    uint32_t p3 = (uint32_t)f.w & 1u;
    if (((g & (CH_ROW - 1)) == 0) && tid == 0) p0 = 0u;   // flips[:,0] never applied

    const uint32_t tp   = p0 ^ p1 ^ p2 ^ p3;
    const uint32_t mask = __ballot_sync(0xffffffffu, tp);
    const uint32_t lanePref = (uint32_t)__popc(mask & ltmask) & 1u;
    const uint32_t wtot     = (uint32_t)__popc(mask) & 1u;

    __shared__ uint32_t sW[32];
    if (lane == 0) sW[warp] = wtot;
    __syncthreads();

    uint32_t before = 0u, total = 0u;
#pragma unroll
    for (int w = 0; w < 32; ++w) {
        uint32_t v = sW[w];
        total ^= v;
        if (w < warp) before ^= v;
    }
    const uint32_t excl = before ^ lanePref;    // chunk-flip parity before this group

    g_packed[(size_t)g * 1024 + tid] =
        (unsigned char)(p0 | (p1 << 1) | (p2 << 2) | (p3 << 3) | (excl << 4));
    if (tid == 0) g_chunkpar[g] = total;
}

// ---------------------------------------------------------------------------
// Kernel 2: pure map with smem-staged edc window.
// 256 threads / CTA, 4 outputs / thread -> 1024 outputs per CTA, always inside
// one chunk (and one row). grid = NGROUPS/256 = 32768.
// edc window [u0, u0+1024] staged as exactly 257 aligned float4 (in-bounds for
// every CTA incl. the last: ub+1028 <= 256*131073). Consumers do 2 conflict-
// free LDS.128 + uniform select by delta = row % 4.
// ---------------------------------------------------------------------------
__global__ void __launch_bounds__(256)
amp_kernel(const float* __restrict__ edc, float* __restrict__ out)
{
    const int blk  = blockIdx.x;
    const int tid  = threadIdx.x;
    const int gidx = blk * 256 + tid;            // group id

    const int chunk = (blk * 256) >> 10;         // uniform per CTA
    const int row   = chunk >> 5;                // uniform
    const int c     = chunk & (CH_ROW - 1);      // uniform

    // Prefix parity over preceding chunks of this row: one ballot over the
    // 32 L1/L2-resident chunk parities.
    const uint32_t par  = g_chunkpar[(row << 5) + (tid & 31)] & 1u;
    const uint32_t bal  = __ballot_sync(0xffffffffu, par != 0u);
    const uint32_t pref = (uint32_t)__popc(bal & ((1u << c) - 1u)) & 1u;

    const unsigned char b = g_packed[gidx];

    // Stage edc window. u0 = flat edc offset of first output of CTA.
    const long long t0    = (long long)blk * 1024;     // first output index
    const long long u0    = t0 + row;                  // edc flat = t + row
    const long long ub    = u0 & ~3LL;                 // 16B-aligned down
    const int       delta = (int)(u0 - ub);            // = row & 3, uniform

    __shared__ float s[257 * 4 + 4];
    const float4* src = reinterpret_cast<const float4*>(edc + ub);
    {
        float4* dst = reinterpret_cast<float4*>(s);
        dst[tid] = __ldg(src + tid);                       // 0..255
        if (tid == 0) dst[256] = __ldg(src + 256);         // 256th
    }
    __syncthreads();

    // Two aligned conflict-free LDS.128 per thread, then uniform select.
    const float4 A  = reinterpret_cast<const float4*>(s)[tid];
    const float4 Bv = reinterpret_cast<const float4*>(s)[tid + 1];

    float e0, e1, e2, e3, e4;
    switch (delta) {
    case 0:  e0 = A.x; e1 = A.y; e2 = A.z; e3 = A.w; e4 = Bv.x; break;
    case 1:  e0 = A.y; e1 = A.z; e2 = A.w; e3 = Bv.x; e4 = Bv.y; break;
    case 2:  e0 = A.z; e1 = A.w; e2 = Bv.x; e3 = Bv.y; e4 = Bv.z; break;
    default: e0 = A.w; e1 = Bv.x; e2 = Bv.y; e3 = Bv.z; e4 = Bv.w; break;
    }

    uint32_t run = pref ^ (((uint32_t)b >> 4) & 1u);
    float4 o;
    run ^= (uint32_t)b & 1u;
    o.x = __uint_as_float(__float_as_uint(sqrtf(fmaxf(e0 - e1, 0.0f))) ^ (run << 31));
    run ^= ((uint32_t)b >> 1) & 1u;
    o.y = __uint_as_float(__float_as_uint(sqrtf(fmaxf(e1 - e2, 0.0f))) ^ (run << 31));
    run ^= ((uint32_t)b >> 2) & 1u;
    o.z = __uint_as_float(__float_as_uint(sqrtf(fmaxf(e2 - e3, 0.0f))) ^ (run << 31));
    run ^= ((uint32_t)b >> 3) & 1u;
    o.w = __uint_as_float(__float_as_uint(sqrtf(fmaxf(e3 - e4, 0.0f))) ^ (run << 31));

    reinterpret_cast<float4*>(out)[gidx] = o;
}

// ---------------------------------------------------------------------------
// Generic fallback: any (B, T). One CTA per row, chunked block-wide parity
// scan with a carried prefix. Only used if sizes don't match the constants.
// ---------------------------------------------------------------------------
__global__ void sticky_sign_generic(const float* __restrict__ edc,
                                    const int*   __restrict__ flips,
                                    float*       __restrict__ out,
                                    int T)
{
    const int row  = blockIdx.x;
    const int n    = T - 1;
    const int tid  = threadIdx.x;
    const int lane = tid & 31;
    const int warp = tid >> 5;

    const float* erow = edc   + (size_t)row * T;
    const int*   frow = flips + (size_t)row * n;
    float*       orow = out   + (size_t)row * n;

    __shared__ uint32_t sW[32];
    __shared__ uint32_t sCarry;
    if (tid == 0) sCarry = 0u;
    const int nwarps = (blockDim.x + 31) >> 5;
    if (tid < 32) sW[tid] = 0u;
    __syncthreads();

    for (int base = 0; base < n; base += blockDim.x) {
        const int i = base + tid;
        uint32_t f = 0u;
        if (i < n && i > 0) f = (uint32_t)frow[i] & 1u;

        const uint32_t m = __ballot_sync(0xffffffffu, f);
        const uint32_t laneIncl = (uint32_t)__popc(m & ((2u << lane) - 1u)) & 1u;
        if (lane == 0) sW[warp] = (uint32_t)__popc(m) & 1u;
        __syncthreads();

        uint32_t wpre = 0u, tot = 0u;
        for (int w = 0; w < nwarps; ++w) {
            uint32_t v = sW[w];
            tot ^= v;
            if (w < warp) wpre ^= v;
        }
        const uint32_t carry = sCarry;
        const uint32_t incl  = carry ^ wpre ^ laneIncl;

        if (i < n) {
            float amp = sqrtf(fmaxf(erow[i] - erow[i + 1], 0.0f));
            orow[i] = __uint_as_float(__float_as_uint(amp) ^ (incl << 31));
        }
        __syncthreads();
        if (tid == 0) sCarry = carry ^ tot;
        __syncthreads();
    }
}

extern "C" void kernel_launch(void* const* d_in, const int* in_sizes, int n_in,
                              void* d_out, int out_size)
{
    // Identify inputs by element count (edc has B extra elements).
    long long n0 = in_sizes[0];
    long long n1 = (n_in > 1) ? in_sizes[1] : 0;

    const float* edc;
    const int*   flips;
    long long ne, nf;
    if (n0 >= n1) {
        edc = (const float*)d_in[0];  flips = (const int*)d_in[1];
        ne = n0; nf = n1;
    } else {
        edc = (const float*)d_in[1];  flips = (const int*)d_in[0];
        ne = n1; nf = n0;
    }
    float* out = (float*)d_out;

    if (ne == (long long)NROWS * TROW && nf == (long long)NROWS * TM1) {
        pack_kernel<<<NCHUNKS, 1024>>>(flips);
        amp_kernel<<<(int)(NGROUPS / 256), 256>>>(edc, out);
    } else {
        long long B = ne - nf;
        if (B <= 0) B = 1;
        int T = (int)(ne / B);
        sticky_sign_generic<<<(int)B, 256>>>(edc, flips, out, T);
    }
}

// round 8
// speedup vs baseline: 1.6482x; 1.6482x over previous
#include <cuda_runtime.h>
#include <cstdint>

#define NROWS   256
#define TM1     131072                    // outputs per row
#define TROW    131073                    // edc row length
#define NGROUPS ((size_t)NROWS * TM1 / 4) // 8,388,608 4-output groups

// Scratch (static device arrays — no runtime allocation).
// g_packed byte: bits[0:3] = 4 flip bits of the group,
//                bit 4     = exclusive flip-parity of the group within its
//                            4096-flip span (one warp's coverage in K1)
__device__ unsigned char g_packed[NGROUPS];   // 8.4 MB
// g_spanpref[row] bit s = parity of all flips of row before span s (32 spans/row)
__device__ unsigned int  g_spanpref[NROWS];   // 1 KB, fully rewritten each launch

__device__ __forceinline__ float sqrt_approx(float x) {
    float r;
    asm("sqrt.approx.f32 %0, %1;" : "=f"(r) : "f"(x));
    return r;
}

// ---------------------------------------------------------------------------
// K1: one CTA per row (1024 thr). Warp w owns flips [w*4096, (w+1)*4096) of
// the row; 32 iterations of lane-coalesced int4 loads. Emits packed bytes
// with in-span exclusive parity (running ballot), then a single 32-wide shfl
// scan (warp 0 only) publishes the per-span row-prefix word.
// ---------------------------------------------------------------------------
__global__ void __launch_bounds__(1024)
scan_pack_kernel(const int* __restrict__ flips)
{
    const int row  = blockIdx.x;
    const int tid  = threadIdx.x;
    const int lane = tid & 31;
    const int warp = tid >> 5;
    const uint32_t ltmask = (1u << lane) - 1u;

    const int4* base = reinterpret_cast<const int4*>(flips + (size_t)row * TM1)
                       + warp * 1024;                      // 1024 int4 per warp
    unsigned char* pbase = g_packed + (size_t)row * (TM1 / 4) + warp * 1024;

    uint32_t run = 0u;   // parity of this warp's flips processed so far
#pragma unroll 4
    for (int i = 0; i < 32; ++i) {
        const int4 f = __ldg(base + i * 32 + lane);
        uint32_t p0 = (uint32_t)f.x & 1u;
        const uint32_t p1 = (uint32_t)f.y & 1u;
        const uint32_t p2 = (uint32_t)f.z & 1u;
        const uint32_t p3 = (uint32_t)f.w & 1u;
        if (tid == 0 && i == 0) p0 = 0u;          // flips[:,0] never applied

        const uint32_t nib = p0 | (p1 << 1) | (p2 << 2) | (p3 << 3);
        const uint32_t gp  = p0 ^ p1 ^ p2 ^ p3;
        const uint32_t bal = __ballot_sync(0xffffffffu, gp != 0u);
        const uint32_t excl = run ^ ((uint32_t)__popc(bal & ltmask) & 1u);
        pbase[i * 32 + lane] = (unsigned char)(nib | (excl << 4));
        run ^= (uint32_t)__popc(bal) & 1u;
    }

    // Cross-warp: exclusive prefix parity per span -> one word per row.
    __shared__ uint32_t sW[32];
    if (lane == 0) sW[warp] = run;      // run identical across lanes of warp
    __syncthreads();

    if (warp == 0) {
        const uint32_t v = sW[lane];
        uint32_t x = v;                  // inclusive XOR scan over 32 warps
#pragma unroll
        for (int d = 1; d < 32; d <<= 1) {
            const uint32_t y = __shfl_up_sync(0xffffffffu, x, d);
            if (lane >= d) x ^= y;
        }
        const uint32_t excl = (x ^ v) & 1u;     // exclusive prefix for span=lane
        const uint32_t word = __ballot_sync(0xffffffffu, excl != 0u);
        if (lane == 0) g_spanpref[row] = word;
    }
}

// ---------------------------------------------------------------------------
// K2: pure map, 4 outputs / thread, no smem, no syncs, 32-bit math.
// CTA = 256 thr = 1024 outputs, always inside one 4096-output span and one
// row. grid = 32768.
// ---------------------------------------------------------------------------
__global__ void __launch_bounds__(256)
amp_kernel(const float* __restrict__ edc, float* __restrict__ out)
{
    const int blk  = blockIdx.x;
    const int tid  = threadIdx.x;
    const int gidx = blk * 256 + tid;            // group id (4 outputs)

    const int row  = blk >> 7;                   // 128 CTAs per row
    const int span = (blk & 127) >> 2;           // 4 CTAs per span

    const uint32_t pref = (g_spanpref[row] >> span) & 1u;
    const uint32_t b    = (uint32_t)g_packed[gidx];

    // edc flat offset of first output = 4*gidx + row (TROW = TM1 + 1)
    const unsigned u0    = ((unsigned)gidx << 2) + (unsigned)row;
    const unsigned ub    = u0 & ~3u;             // 16B-aligned down
    const int      delta = row & 3;              // uniform per CTA

    const float4* ep = reinterpret_cast<const float4*>(edc) + (ub >> 2);
    const float4 A = __ldg(ep);                  // w0..w3
    const float4 B = __ldg(ep + 1);              // w4..w7  (last read = edc end-1)

    float e0, e1, e2, e3, e4;
    switch (delta) {
    case 0:  e0 = A.x; e1 = A.y; e2 = A.z; e3 = A.w; e4 = B.x; break;
    case 1:  e0 = A.y; e1 = A.z; e2 = A.w; e3 = B.x; e4 = B.y; break;
    case 2:  e0 = A.z; e1 = A.w; e2 = B.x; e3 = B.y; e4 = B.z; break;
    default: e0 = A.w; e1 = B.x; e2 = B.y; e3 = B.z; e4 = B.w; break;
    }

    uint32_t run = pref ^ ((b >> 4) & 1u);
    float4 o;
    run ^= b & 1u;
    o.x = __uint_as_float(__float_as_uint(sqrt_approx(fmaxf(e0 - e1, 0.0f))) ^ (run << 31));
    run ^= (b >> 1) & 1u;
    o.y = __uint_as_float(__float_as_uint(sqrt_approx(fmaxf(e1 - e2, 0.0f))) ^ (run << 31));
    run ^= (b >> 2) & 1u;
    o.z = __uint_as_float(__float_as_uint(sqrt_approx(fmaxf(e2 - e3, 0.0f))) ^ (run << 31));
    run ^= (b >> 3) & 1u;
    o.w = __uint_as_float(__float_as_uint(sqrt_approx(fmaxf(e3 - e4, 0.0f))) ^ (run << 31));

    reinterpret_cast<float4*>(out)[gidx] = o;
}

// ---------------------------------------------------------------------------
// Generic fallback: any (B, T). One CTA per row, chunked block-wide parity
// scan with a carried prefix. Only used if sizes don't match the constants.
// ---------------------------------------------------------------------------
__global__ void sticky_sign_generic(const float* __restrict__ edc,
                                    const int*   __restrict__ flips,
                                    float*       __restrict__ out,
                                    int T)
{
    const int row  = blockIdx.x;
    const int n    = T - 1;
    const int tid  = threadIdx.x;
    const int lane = tid & 31;
    const int warp = tid >> 5;

    const float* erow = edc   + (size_t)row * T;
    const int*   frow = flips + (size_t)row * n;
    float*       orow = out   + (size_t)row * n;

    __shared__ uint32_t sW[32];
    __shared__ uint32_t sCarry;
    if (tid == 0) sCarry = 0u;
    const int nwarps = (blockDim.x + 31) >> 5;
    if (tid < 32) sW[tid] = 0u;
    __syncthreads();

    for (int base = 0; base < n; base += blockDim.x) {
        const int i = base + tid;
        uint32_t f = 0u;
        if (i < n && i > 0) f = (uint32_t)frow[i] & 1u;

        const uint32_t m = __ballot_sync(0xffffffffu, f);
        const uint32_t laneIncl = (uint32_t)__popc(m & ((2u << lane) - 1u)) & 1u;
        if (lane == 0) sW[warp] = (uint32_t)__popc(m) & 1u;
        __syncthreads();

        uint32_t wpre = 0u, tot = 0u;
        for (int w = 0; w < nwarps; ++w) {
            uint32_t v = sW[w];
            tot ^= v;
            if (w < warp) wpre ^= v;
        }
        const uint32_t carry = sCarry;
        const uint32_t incl  = carry ^ wpre ^ laneIncl;

        if (i < n) {
            float amp = sqrtf(fmaxf(erow[i] - erow[i + 1], 0.0f));
            orow[i] = __uint_as_float(__float_as_uint(amp) ^ (incl << 31));
        }
        __syncthreads();
        if (tid == 0) sCarry = carry ^ tot;
        __syncthreads();
    }
}

extern "C" void kernel_launch(void* const* d_in, const int* in_sizes, int n_in,
                              void* d_out, int out_size)
{
    // Identify inputs by element count (edc has B extra elements).
    long long n0 = in_sizes[0];
    long long n1 = (n_in > 1) ? in_sizes[1] : 0;

    const float* edc;
    const int*   flips;
    long long ne, nf;
    if (n0 >= n1) {
        edc = (const float*)d_in[0];  flips = (const int*)d_in[1];
        ne = n0; nf = n1;
    } else {
        edc = (const float*)d_in[1];  flips = (const int*)d_in[0];
        ne = n1; nf = n0;
    }
    float* out = (float*)d_out;

    if (ne == (long long)NROWS * TROW && nf == (long long)NROWS * TM1) {
        scan_pack_kernel<<<NROWS, 1024>>>(flips);
        amp_kernel<<<(int)(NGROUPS / 256), 256>>>(edc, out);
    } else {
        long long B = ne - nf;
        if (B <= 0) B = 1;
        int T = (int)(ne / B);
        sticky_sign_generic<<<(int)B, 256>>>(edc, flips, out, T);
    }
}